// round 10
// baseline (speedup 1.0000x reference)
#include <cuda_runtime.h>
#include <cstdint>

#define DD 160
#define NN 82944
#define BB 4
#define NT 128              /* tile width (columns) */
#define RS 128              /* tile row stride in floats (512B) */
#define EPSV 1e-6f

#define NTH 256             /* threads per step block */
#define PBLKS 144           /* persistent blocks (144 x 18 = 2592 tiles) */
#define TPB 18              /* tiles per block */
#define BLKS_PER_B 36       /* blocks per batch */
#define TILEF (DD * RS)     /* floats per tile buffer (80 KB) */
#define TILE_BYTES (TILEF * 4)

#define NBLKF 81            /* NN / 1024 for float4x256 final kernel */

// Scratch state (device globals: no allocation allowed)
__device__ float g_c[BB * NN];                 // coef
__device__ float g_v[BB * DD];                 // bases vector
__device__ float g_s[BB];                      // ||v||^2
__device__ float g_wp[BB * BLKS_PER_B * DD];   // per-persistent-block w partials
__device__ float g_tp[BB * BLKS_PER_B];        // per-persistent-block t partials

// ---------------------------------------------------------------------------
// TMA-lite: cp.async.bulk (UBLKCP) + mbarrier helpers
// ---------------------------------------------------------------------------
__device__ __forceinline__ void mbar_init(uint32_t mbar, uint32_t cnt) {
    asm volatile("mbarrier.init.shared.b64 [%0], %1;" :: "r"(mbar), "r"(cnt) : "memory");
}
__device__ __forceinline__ void mbar_inval(uint32_t mbar) {
    asm volatile("mbarrier.inval.shared.b64 [%0];" :: "r"(mbar) : "memory");
}
__device__ __forceinline__ void mbar_expect_tx(uint32_t mbar, uint32_t bytes) {
    asm volatile("mbarrier.arrive.expect_tx.shared.b64 _, [%0], %1;"
                 :: "r"(mbar), "r"(bytes) : "memory");
}
__device__ __forceinline__ void mbar_wait(uint32_t mbar, uint32_t parity) {
    uint32_t done;
    asm volatile(
        "{\n\t.reg .pred p;\n\t"
        "mbarrier.try_wait.parity.acquire.cta.shared::cta.b64 p, [%1], %2;\n\t"
        "selp.b32 %0, 1, 0, p;\n\t}"
        : "=r"(done) : "r"(mbar), "r"(parity) : "memory");
    if (!done) {
        asm volatile(
            "{\n\t.reg .pred P1;\n\t"
            "WL_%=:\n\t"
            "mbarrier.try_wait.parity.acquire.cta.shared::cta.b64 P1, [%0], %1, 0x989680;\n\t"
            "@P1 bra.uni WD_%=;\n\t"
            "bra.uni WL_%=;\n\t"
            "WD_%=:\n\t}"
            :: "r"(mbar), "r"(parity) : "memory");
    }
}
__device__ __forceinline__ void bulk_copy(uint32_t dst, const void* src,
                                          uint32_t bytes, uint32_t mbar) {
    asm volatile(
        "cp.async.bulk.shared::cluster.global.mbarrier::complete_tx::bytes "
        "[%0], [%1], %2, [%3];"
        :: "r"(dst), "l"(src), "r"(bytes), "r"(mbar) : "memory");
}

// ---------------------------------------------------------------------------
// init: v = bases, s = ||v||^2
// ---------------------------------------------------------------------------
__global__ void init_kernel(const float* __restrict__ bases) {
    int b = blockIdx.x, d = threadIdx.x;
    __shared__ float sh[DD];
    float v = bases[b * DD + d];
    g_v[b * DD + d] = v;
    sh[d] = v * v;
    __syncthreads();
    if (d == 0) {
        float s = 0.f;
        for (int i = 0; i < DD; i++) s += sh[i];
        g_s[b] = s;
    }
}

// ---------------------------------------------------------------------------
// One NMF step: persistent 256-thread blocks, double-buffered cp.async.bulk.
// 160 bulk row-copies per tile (warp 0, 5 per lane). w/t accumulate in
// registers across all 18 tiles; shuffles only once per step.
// ---------------------------------------------------------------------------
__global__ void __launch_bounds__(NTH, 1) step_kernel(const float* __restrict__ x,
                                                      int first) {
    __shared__ float v_sh[DD];
    __shared__ float c_sh[NT];
    __shared__ float u_half[NTH];
    __shared__ float red[4];
    __shared__ __align__(8) unsigned long long mbar_s[2];
    extern __shared__ float buf[];  // 2 * TILEF floats = 160 KB

    int p = blockIdx.x, tid = threadIdx.x;
    int lane = tid & 31, wid = tid >> 5;
    int b = p / BLKS_PER_B;
    int pb = p % BLKS_PER_B;
    int blk0 = pb * TPB;

    uint32_t mb0 = (uint32_t)__cvta_generic_to_shared(&mbar_s[0]);
    uint32_t mb1 = (uint32_t)__cvta_generic_to_shared(&mbar_s[1]);
    uint32_t sbase = (uint32_t)__cvta_generic_to_shared(buf);

    if (tid == 0) { mbar_init(mb0, 1); mbar_init(mb1, 1); }
    for (int i = tid; i < DD; i += NTH) v_sh[i] = g_v[b * DD + i];
    float s = g_s[b];
    __syncthreads();

    const float* gtile = x + (size_t)b * DD * NN;

#define ISSUE_TILE(t)                                                         \
    do {                                                                      \
        if (tid < 32) {                                                       \
            uint32_t mb = ((t) & 1) ? mb1 : mb0;                              \
            if (tid == 0) mbar_expect_tx(mb, TILE_BYTES);                     \
            uint32_t sd = sbase + (uint32_t)(((t) & 1) * TILE_BYTES);         \
            const float* gs = gtile + (size_t)(blk0 + (t)) * NT;              \
            _Pragma("unroll")                                                 \
            for (int k = 0; k < 5; k++) {                                     \
                int row = tid + 32 * k;                                       \
                bulk_copy(sd + (uint32_t)(row * RS) * 4u,                     \
                          gs + (size_t)row * NN, 512u, mb);                   \
            }                                                                 \
        }                                                                     \
    } while (0)

    int half = tid >> 7;           // 0: rows 0..79, 1: rows 80..159
    int hoff = half * 80;
    int col = tid & 127;

    float acc[20];                 // pass-2 accumulators (20 rows per warp)
#pragma unroll
    for (int k = 0; k < 20; k++) acc[k] = 0.f;
    float tacc = 0.f;

    ISSUE_TILE(0);

    for (int i = 0; i < TPB; i++) {
        if (i + 1 < TPB) ISSUE_TILE(i + 1);
        mbar_wait((i & 1) ? mb1 : mb0, (i >> 1) & 1);
        __syncthreads();  // all warps see completed tile

        const float* tile = buf + (i & 1) * TILEF;
        int blk = blk0 + i;

        // ---- Pass 1: partial u over this thread's 80 rows of column `col`
        const float* tp = tile + hoff * RS + col;
        const float* vp = v_sh + hoff;
        float u0 = 0.f, u1 = 0.f, u2 = 0.f, u3 = 0.f;
#pragma unroll
        for (int d = 0; d < 80; d += 4) {
            u0 = fmaf(tp[(d + 0) * RS], vp[d + 0], u0);
            u1 = fmaf(tp[(d + 1) * RS], vp[d + 1], u1);
            u2 = fmaf(tp[(d + 2) * RS], vp[d + 2], u2);
            u3 = fmaf(tp[(d + 3) * RS], vp[d + 3], u3);
        }
        u_half[tid] = (u0 + u1) + (u2 + u3);
        __syncthreads();

        // ---- combine halves, update c (threads 0..127)
        if (tid < NT) {
            float u = u_half[tid] + u_half[tid + NT];
            size_t cidx = (size_t)b * NN + (size_t)blk * NT + tid;
            float cold = first ? 1.f : g_c[cidx];
            float cn = cold * u / (cold * s + EPSV);
            g_c[cidx] = cn;
            c_sh[tid] = cn;
            tacc = fmaf(cn, cn, tacc);
        }
        __syncthreads();

        // ---- Pass 2: accumulate w partials in registers (no shuffles here)
        const float4 cc = *reinterpret_cast<const float4*>(&c_sh[lane * 4]);
        const float* rp = tile + (wid * 20) * RS + lane * 4;
#pragma unroll
        for (int k = 0; k < 20; k++) {
            float4 xv = *reinterpret_cast<const float4*>(rp + k * RS);
            acc[k] = fmaf(xv.x, cc.x,
                     fmaf(xv.y, cc.y, fmaf(xv.z, cc.z, fmaf(xv.w, cc.w, acc[k]))));
        }
        __syncthreads();  // protect buffer + c_sh before next issue/overwrite
    }
#undef ISSUE_TILE

    // ---- end-of-step reductions (once per block)
    if (tid < NT) {
#pragma unroll
        for (int off = 16; off; off >>= 1)
            tacc += __shfl_xor_sync(0xffffffffu, tacc, off);
        if (lane == 0) red[wid] = tacc;
    }
    __syncthreads();
    if (tid == 0) g_tp[b * BLKS_PER_B + pb] = red[0] + red[1] + red[2] + red[3];

    float* wp = g_wp + (size_t)(b * BLKS_PER_B + pb) * DD;
#pragma unroll
    for (int k = 0; k < 20; k++) {
        float a = acc[k];
#pragma unroll
        for (int off = 16; off; off >>= 1)
            a += __shfl_xor_sync(0xffffffffu, a, off);
        if (lane == 0) wp[wid * 20 + k] = a;
    }

    __syncthreads();
    if (tid == 0) { mbar_inval(mb0); mbar_inval(mb1); }
}

// ---------------------------------------------------------------------------
// v update: sum 36 partials, v = v*w/(v*t+eps), s = ||v||^2
// ---------------------------------------------------------------------------
__global__ void vupdate_kernel() {
    __shared__ float shs[DD];
    __shared__ float tsh;
    int b = blockIdx.x, tid = threadIdx.x;  // 160 threads

    float w = 0.f;
    for (int j = 0; j < BLKS_PER_B; j++)
        w += g_wp[(size_t)(b * BLKS_PER_B + j) * DD + tid];
    if (tid == 0) {
        float t = 0.f;
        for (int j = 0; j < BLKS_PER_B; j++) t += g_tp[b * BLKS_PER_B + j];
        tsh = t;
    }
    __syncthreads();

    float vd = g_v[b * DD + tid];
    float vn = vd * w / (vd * tsh + EPSV);
    g_v[b * DD + tid] = vn;
    shs[tid] = vn * vn;
    __syncthreads();
    if (tid == 0) {
        float s = 0.f;
        for (int i = 0; i < DD; i++) s += shs[i];
        g_s[b] = s;
    }
}

// ---------------------------------------------------------------------------
// Final: u = X^T v, c' = c*u/(c*s+eps), out = v c'^T.
// float4 per thread, 256-thread blocks.
// ---------------------------------------------------------------------------
__global__ void __launch_bounds__(256) final_kernel(const float* __restrict__ x,
                                                    float* __restrict__ out) {
    __shared__ float v_sh[DD];
    int b = blockIdx.y, tid = threadIdx.x;
    size_t n0 = (size_t)blockIdx.x * 1024 + (size_t)tid * 4;

    for (int i = tid; i < DD; i += 256) v_sh[i] = g_v[b * DD + i];
    __syncthreads();
    float s = g_s[b];

    const float* xb = x + (size_t)b * DD * NN + n0;
    float* ob = out + (size_t)b * DD * NN + n0;

    float4 u = make_float4(0.f, 0.f, 0.f, 0.f);
#pragma unroll 8
    for (int d = 0; d < DD; d++) {
        float4 xv = *reinterpret_cast<const float4*>(xb + (size_t)d * NN);
        float vd = v_sh[d];
        u.x = fmaf(xv.x, vd, u.x);
        u.y = fmaf(xv.y, vd, u.y);
        u.z = fmaf(xv.z, vd, u.z);
        u.w = fmaf(xv.w, vd, u.w);
    }

    float4 co = *reinterpret_cast<const float4*>(g_c + (size_t)b * NN + n0);
    float4 cn;
    cn.x = co.x * u.x / (co.x * s + EPSV);
    cn.y = co.y * u.y / (co.y * s + EPSV);
    cn.z = co.z * u.z / (co.z * s + EPSV);
    cn.w = co.w * u.w / (co.w * s + EPSV);

#pragma unroll 8
    for (int d = 0; d < DD; d++) {
        float vd = v_sh[d];
        float4 o = make_float4(vd * cn.x, vd * cn.y, vd * cn.z, vd * cn.w);
        *reinterpret_cast<float4*>(ob + (size_t)d * NN) = o;
    }
}

// ---------------------------------------------------------------------------
extern "C" void kernel_launch(void* const* d_in, const int* in_sizes, int n_in,
                              void* d_out, int out_size) {
    const float* x = (const float*)d_in[0];
    const float* bases = (const float*)d_in[1];
    float* out = (float*)d_out;

    cudaFuncSetAttribute(step_kernel, cudaFuncAttributeMaxDynamicSharedMemorySize,
                         2 * TILE_BYTES);

    init_kernel<<<BB, DD>>>(bases);
    for (int s = 0; s < 4; s++) {
        step_kernel<<<PBLKS, NTH, 2 * TILE_BYTES>>>(x, s == 0);
        vupdate_kernel<<<BB, DD>>>();
    }
    final_kernel<<<dim3(NBLKF, BB), 256>>>(x, out);
}

// round 11
// speedup vs baseline: 2.6096x; 2.6096x over previous
#include <cuda_runtime.h>
#include <cstdint>

#define DD 160
#define NN 82944
#define BB 4
#define WTILE 128           /* columns per tile */
#define G 4                 /* d-groups per column */
#define DG 40               /* rows per group */
#define NTH 512             /* G * WTILE */
#define PBLKS 144           /* persistent blocks (144 x 18 = 2592 tiles) */
#define TPB 18              /* tiles per block */
#define BLKS_PER_B 36       /* blocks per batch */
#define EPSV 1e-6f
#define NBLKF 81            /* NN / 1024 for float4x256 final kernel */

// Scratch state (device globals: no allocation allowed)
__device__ float g_c[BB * NN];                 // coef
__device__ float g_v[BB * DD];                 // bases vector
__device__ float g_s[BB];                      // ||v||^2
__device__ float g_wp[BB * BLKS_PER_B * DD];   // per-block w partials
__device__ float g_tp[BB * BLKS_PER_B];        // per-block t partials

// ---------------------------------------------------------------------------
// init: v = bases, s = ||v||^2
// ---------------------------------------------------------------------------
__global__ void init_kernel(const float* __restrict__ bases) {
    int b = blockIdx.x, d = threadIdx.x;
    __shared__ float sh[DD];
    float v = bases[b * DD + d];
    g_v[b * DD + d] = v;
    sh[d] = v * v;
    __syncthreads();
    if (d == 0) {
        float s = 0.f;
        for (int i = 0; i < DD; i++) s += sh[i];
        g_s[b] = s;
    }
}

// ---------------------------------------------------------------------------
// One NMF step: X lives in registers between the two passes. Thread (g,c)
// loads X[g*40..g*40+40, col] once (coalesced LDG), contributes a u-partial,
// gets c_new via a small SMEM exchange, then folds the SAME registers into
// register-resident w accumulators. X never touches SMEM.
// ---------------------------------------------------------------------------
__global__ void __launch_bounds__(NTH, 1) step_kernel(const float* __restrict__ x,
                                                      int first) {
    __shared__ float v_sh[DD];
    __shared__ float u_sh[NTH];
    __shared__ float c_sh[WTILE];
    __shared__ float wred[16][DG];
    __shared__ float tred[4];

    int p = blockIdx.x, tid = threadIdx.x;
    int lane = tid & 31, wrp = tid >> 5;
    int g = tid >> 7;            // d-group 0..3
    int c = tid & 127;           // column within tile
    int b = p / BLKS_PER_B, pb = p % BLKS_PER_B;
    int blk0 = pb * TPB;

    for (int i = tid; i < DD; i += NTH) v_sh[i] = g_v[b * DD + i];
    float s = g_s[b];
    __syncthreads();

    const float* xp0 = x + ((size_t)b * DD + g * DG) * NN
                         + (size_t)blk0 * WTILE + c;
    const float* vg = v_sh + g * DG;

    float wacc[DG];
#pragma unroll
    for (int k = 0; k < DG; k++) wacc[k] = 0.f;
    float tacc = 0.f;

    for (int i = 0; i < TPB; i++) {
        const float* xp = xp0 + (size_t)i * WTILE;

        // ---- load 40 rows of this column into registers (batched LDGs)
        float xr[DG];
#pragma unroll
        for (int k = 0; k < DG; k++) xr[k] = xp[(size_t)k * NN];

        // ---- u partial
        float u0 = 0.f, u1 = 0.f, u2 = 0.f, u3 = 0.f;
#pragma unroll
        for (int k = 0; k < DG; k += 4) {
            u0 = fmaf(xr[k + 0], vg[k + 0], u0);
            u1 = fmaf(xr[k + 1], vg[k + 1], u1);
            u2 = fmaf(xr[k + 2], vg[k + 2], u2);
            u3 = fmaf(xr[k + 3], vg[k + 3], u3);
        }
        u_sh[tid] = (u0 + u1) + (u2 + u3);
        __syncthreads();

        // ---- combine 4 group-partials, update c (threads 0..127)
        if (tid < WTILE) {
            float u = u_sh[tid] + u_sh[tid + 128] + u_sh[tid + 256] + u_sh[tid + 384];
            size_t cidx = (size_t)b * NN + (size_t)(blk0 + i) * WTILE + tid;
            float cold = first ? 1.f : g_c[cidx];
            float cn = cold * u / (cold * s + EPSV);
            g_c[cidx] = cn;
            c_sh[tid] = cn;
            tacc = fmaf(cn, cn, tacc);
        }
        __syncthreads();

        // ---- fold registers into w accumulators
        float cn = c_sh[c];
#pragma unroll
        for (int k = 0; k < DG; k++) wacc[k] = fmaf(xr[k], cn, wacc[k]);
        // c_sh is rewritten only after next iteration's __syncthreads -> safe
    }

    // ---- end-of-step reductions (once per block)
    if (tid < WTILE) {
#pragma unroll
        for (int off = 16; off; off >>= 1)
            tacc += __shfl_xor_sync(0xffffffffu, tacc, off);
        if (lane == 0) tred[wrp] = tacc;
    }
#pragma unroll
    for (int k = 0; k < DG; k++) {
        float a = wacc[k];
#pragma unroll
        for (int off = 16; off; off >>= 1)
            a += __shfl_xor_sync(0xffffffffu, a, off);
        if (lane == 0) wred[wrp][k] = a;
    }
    __syncthreads();
    if (tid == 0)
        g_tp[b * BLKS_PER_B + pb] = tred[0] + tred[1] + tred[2] + tred[3];
    if (tid < DD) {
        int gg = tid / DG, k = tid % DG;
        g_wp[(size_t)(b * BLKS_PER_B + pb) * DD + tid] =
            wred[4 * gg + 0][k] + wred[4 * gg + 1][k] +
            wred[4 * gg + 2][k] + wred[4 * gg + 3][k];
    }
}

// ---------------------------------------------------------------------------
// v update: sum 36 partials, v = v*w/(v*t+eps), s = ||v||^2
// ---------------------------------------------------------------------------
__global__ void vupdate_kernel() {
    __shared__ float shs[DD];
    __shared__ float tsh;
    int b = blockIdx.x, tid = threadIdx.x;  // 160 threads

    float w = 0.f;
    for (int j = 0; j < BLKS_PER_B; j++)
        w += g_wp[(size_t)(b * BLKS_PER_B + j) * DD + tid];
    if (tid == 0) {
        float t = 0.f;
        for (int j = 0; j < BLKS_PER_B; j++) t += g_tp[b * BLKS_PER_B + j];
        tsh = t;
    }
    __syncthreads();

    float vd = g_v[b * DD + tid];
    float vn = vd * w / (vd * tsh + EPSV);
    g_v[b * DD + tid] = vn;
    shs[tid] = vn * vn;
    __syncthreads();
    if (tid == 0) {
        float s = 0.f;
        for (int i = 0; i < DD; i++) s += shs[i];
        g_s[b] = s;
    }
}

// ---------------------------------------------------------------------------
// Final: u = X^T v, c' = c*u/(c*s+eps), out = v c'^T.
// float4 per thread, 256-thread blocks.
// ---------------------------------------------------------------------------
__global__ void __launch_bounds__(256) final_kernel(const float* __restrict__ x,
                                                    float* __restrict__ out) {
    __shared__ float v_sh[DD];
    int b = blockIdx.y, tid = threadIdx.x;
    size_t n0 = (size_t)blockIdx.x * 1024 + (size_t)tid * 4;

    for (int i = tid; i < DD; i += 256) v_sh[i] = g_v[b * DD + i];
    __syncthreads();
    float s = g_s[b];

    const float* xb = x + (size_t)b * DD * NN + n0;
    float* ob = out + (size_t)b * DD * NN + n0;

    float4 u = make_float4(0.f, 0.f, 0.f, 0.f);
#pragma unroll 8
    for (int d = 0; d < DD; d++) {
        float4 xv = *reinterpret_cast<const float4*>(xb + (size_t)d * NN);
        float vd = v_sh[d];
        u.x = fmaf(xv.x, vd, u.x);
        u.y = fmaf(xv.y, vd, u.y);
        u.z = fmaf(xv.z, vd, u.z);
        u.w = fmaf(xv.w, vd, u.w);
    }

    float4 co = *reinterpret_cast<const float4*>(g_c + (size_t)b * NN + n0);
    float4 cn;
    cn.x = co.x * u.x / (co.x * s + EPSV);
    cn.y = co.y * u.y / (co.y * s + EPSV);
    cn.z = co.z * u.z / (co.z * s + EPSV);
    cn.w = co.w * u.w / (co.w * s + EPSV);

#pragma unroll 8
    for (int d = 0; d < DD; d++) {
        float vd = v_sh[d];
        float4 o = make_float4(vd * cn.x, vd * cn.y, vd * cn.z, vd * cn.w);
        *reinterpret_cast<float4*>(ob + (size_t)d * NN) = o;
    }
}

// ---------------------------------------------------------------------------
extern "C" void kernel_launch(void* const* d_in, const int* in_sizes, int n_in,
                              void* d_out, int out_size) {
    const float* x = (const float*)d_in[0];
    const float* bases = (const float*)d_in[1];
    float* out = (float*)d_out;

    init_kernel<<<BB, DD>>>(bases);
    for (int s = 0; s < 4; s++) {
        step_kernel<<<PBLKS, NTH>>>(x, s == 0);
        vupdate_kernel<<<BB, DD>>>();
    }
    final_kernel<<<dim3(NBLKF, BB), 256>>>(x, out);
}